// round 17
// baseline (speedup 1.0000x reference)
#include <cuda_runtime.h>
#include <cuda_bf16.h>
#include <cstdint>

#define D_DIM 512
#define K_DIM 32
#define P_DIM 528            // K*(K+1)/2 = 33*16
#define MAXN  100352
#define GAMMA 0.01f
#define TOLF  1e-6f
#define GUESS_RATIO (1.0f - 0.001f)

#define NKS   33             // k-steps of 16
#define GS    3              // k-steps per group
#define NG    11             // groups
#define STB   4096           // bytes per k-step tile (128 x 8 u32)
#define GB    (GS * STB)     // 12288 B per group
#define MT    128
#define NMB   784

// ---------------- device scratch ----------------
__device__ float g_kv[MAXN];
__device__ uint32_t g_cover[MAXN / 32];
// B image: [4 nblk][11 grp][3 sl][128 n][8 u32]
__device__ __align__(16) uint32_t g_Vb[4 * NG * GS * 128 * 8];
// H image: [784 mblk][33 ks][128 row][8 u32]
__device__ __align__(16) uint32_t g_H[(size_t)NMB * NKS * 128 * 8];
// U image for rowstats: [32 ks][32 j][8 u32]
__device__ __align__(16) uint32_t g_Ub[32 * 32 * 8];
__device__ float g_xmuU[K_DIM];
__device__ float g_xcU[K_DIM];
__device__ float g_dU[K_DIM];
__device__ float g_change[D_DIM];

// ---------------- PTX helpers ----------------
__device__ __forceinline__ uint32_t smem_u32(const void* p) {
    uint32_t a;
    asm("{ .reg .u64 t; cvta.to.shared.u64 t, %1; cvt.u32.u64 %0, t; }" : "=r"(a) : "l"(p));
    return a;
}
#define MBAR_INIT(a, c) asm volatile("mbarrier.init.shared.b64 [%0], %1;" :: "r"(a), "r"(c) : "memory")
#define MBAR_EXPECT_TX(a, b) asm volatile("mbarrier.arrive.expect_tx.shared.b64 _, [%0], %1;" :: "r"(a), "r"(b) : "memory")
#define MBAR_ARRIVE(a) asm volatile("mbarrier.arrive.shared.b64 _, [%0];" :: "r"(a) : "memory")
#define MBAR_WAIT(a, p) do { \
    uint32_t _m = (a), _p = (p), _d; \
    asm volatile("{ .reg .pred q; mbarrier.try_wait.parity.acquire.cta.shared::cta.b64 q, [%1], %2; selp.b32 %0,1,0,q; }" \
        : "=r"(_d) : "r"(_m), "r"(_p) : "memory"); \
    if (!_d) asm volatile("{ .reg .pred Q; WL%=: mbarrier.try_wait.parity.acquire.cta.shared::cta.b64 Q, [%0], %1, 0x989680; @Q bra.uni WD%=; bra.uni WL%=; WD%=: }" \
        :: "r"(_m), "r"(_p) : "memory"); \
} while (0)
#define FENCE_ASYNC() asm volatile("fence.proxy.async.shared::cta;" ::: "memory")

__device__ __forceinline__ void bulk_g2s(uint32_t dst, const void* src, uint32_t bytes, uint32_t mbar) {
    asm volatile("cp.async.bulk.shared::cta.global.mbarrier::complete_tx::bytes [%0], [%1], %2, [%3];"
        :: "r"(dst), "l"(src), "r"(bytes), "r"(mbar) : "memory");
}
__device__ __forceinline__ void mma16816(float* c, const uint32_t* a, const uint32_t* b) {
    asm volatile("mma.sync.aligned.m16n8k16.row.col.f32.bf16.bf16.f32 "
        "{%0,%1,%2,%3}, {%4,%5,%6,%7}, {%8,%9}, {%0,%1,%2,%3};"
        : "+f"(c[0]), "+f"(c[1]), "+f"(c[2]), "+f"(c[3])
        : "r"(a[0]), "r"(a[1]), "r"(a[2]), "r"(a[3]), "r"(b[0]), "r"(b[1]));
}
__device__ __forceinline__ uint32_t packbf(float a, float b) {
    __nv_bfloat162 r = __float22bfloat162_rn(make_float2(a, b));
    return *(uint32_t*)&r;
}

// ---------------- kernel A: small vectors + bitmap clear ----------------
__global__ void k_init(const float* __restrict__ U,
                       const float* __restrict__ zmu,
                       const float* __restrict__ xc) {
    __shared__ float s_xmuU[K_DIM], s_xcU[K_DIM];
    int t = threadIdx.x;
    for (int i = t; i < MAXN / 32; i += 512) g_cover[i] = 0u;
    if (t < 64) {
        int j = t & 31;
        bool is_mu = t < 32;
        const float* v = is_mu ? zmu : xc;
        float s = 0.f;
        for (int d = 0; d < D_DIM; ++d) s = fmaf(v[d], U[d * K_DIM + j], s);
        if (is_mu) { s_xmuU[j] = s; g_xmuU[j] = s; }
        else       { s_xcU[j]  = s; g_xcU[j]  = s; }
    }
    __syncthreads();
    if (t < 32) g_dU[t] = s_xmuU[t] - s_xcU[t];
    for (int d = t; d < D_DIM; d += blockDim.x) {
        float s = 0.f;
        #pragma unroll
        for (int j = 0; j < K_DIM; ++j)
            s = fmaf(s_xcU[j] - s_xmuU[j], U[d * K_DIM + j], s);
        g_change[d] = xc[d] - zmu[d] - s;
    }
}

// ---------------- kernel P: permuted bf16 V image ----------------
__global__ void k_prepV(const float* __restrict__ V) {
    int pos = threadIdx.x;
    if (pos >= 264) return;
    int d = blockIdx.x;
    int ks = pos >> 3, q = pos & 7;
    int k = ks * 16 + 2 * (q >> 1) + 8 * (q & 1);
    float2 v = *(const float2*)&V[(size_t)d * P_DIM + k];
    int nblk = d >> 7, n = d & 127;
    int grp = ks / GS, sl = ks % GS;
    g_Vb[((((size_t)(nblk * NG + grp) * GS + sl) * 128 + n) * 8) + q] = packbf(v.x, v.y);
}

// ---------------- kernel PU: permuted bf16 U image ----------------
__global__ void k_prepU(const float* __restrict__ U) {
    int idx = blockIdx.x * 256 + threadIdx.x;
    if (idx >= 8192) return;
    int q = idx & 7, j = (idx >> 3) & 31, ks = idx >> 8;
    int d = ks * 16 + 2 * (q >> 1) + 8 * (q & 1);
    g_Ub[idx] = packbf(U[d * K_DIM + j], U[(d + 1) * K_DIM + j]);
}

// ---------------- secant ----------------
__device__ __forceinline__ float secf(float x, float egz, float zp) {
    float t = 1.f - egz * expf(-GAMMA * x);
    return t * t * x - zp;
}

// ------ kernel B: per-row stats via HMMA (+fused secant + fused H gen) ------
#define KSTRIDE 4128
#define RS_A    0             // A tile (33024); later reused as coord (128*34*4)
#define RS_U    33024         // 32768
#define RS_ZMU  65792         // 2048
#define RS_DU   67840         // 128
#define RS_ZN   67968         // 512
#define RS_CHC  68480         // 512
#define RS_IUP  68992         // 1056 -> pad 1088
#define RS_SMEM 70080
#define CRD_S   34            // coord smem row stride (floats, even)

__global__ __launch_bounds__(256, 3) void k_rowstats(
    const float* __restrict__ Z_all, const float* __restrict__ zmu,
    const int* __restrict__ choice, int N) {

    extern __shared__ __align__(16) char rsm[];
    int tid = threadIdx.x;
    int lane = tid & 31, w = tid >> 5;
    int gl = lane >> 2, i4 = lane & 3;
    int n0 = blockIdx.x * 128;

    float* zmuS = (float*)(rsm + RS_ZMU);
    float* dUs  = (float*)(rsm + RS_DU);
    float* s_zn = (float*)(rsm + RS_ZN);
    int*   chcS = (int*)(rsm + RS_CHC);
    uint16_t* iup = (uint16_t*)(rsm + RS_IUP);

    for (int i = tid; i < 512; i += 256) zmuS[i] = zmu[i];
    if (tid < 32) {
        dUs[tid] = g_dU[tid];
        int i = tid;
        int off = i * K_DIM - (i * (i - 1)) / 2;
        for (int j = i; j < K_DIM; ++j)
            iup[off + j - i] = (uint16_t)(i | (j << 8));
    }
    for (int e = tid; e < 2048; e += 256)
        ((uint4*)(rsm + RS_U))[e] = ((const uint4*)g_Ub)[e];
    if (tid < 128) {
        int cc = choice[min(n0 + tid, N - 1)];
        chcS[tid] = cc;
        if (n0 + tid < N) atomicOr(&g_cover[cc >> 5], 1u << (cc & 31));
    }
    __syncthreads();

    float acc[4][4] = {};
    float znp[4] = {};
    int c8 = lane & 7, rq = lane >> 3;

    auto conv = [&](int c) {
        #pragma unroll
        for (int p = 0; p < 4; ++p) {
            int row = p * 32 + w * 4 + rq;
            const float* zrow = Z_all + (size_t)chcS[row] * D_DIM + c * 128;
            #pragma unroll
            for (int i = 0; i < 4; ++i) {
                int col4 = c8 + 8 * i;
                float4 z = *(const float4*)&zrow[col4 * 4];
                float4 m = *(const float4*)&zmuS[c * 128 + col4 * 4];
                float z0 = z.x - m.x, z1 = z.y - m.y, z2 = z.z - m.z, z3 = z.w - m.w;
                znp[p] += z0 * z0 + z1 * z1 + z2 * z2 + z3 * z3;
                int ks = col4 >> 2, kb = (col4 & 3) * 4;
                int q0 = (kb & 6) + (kb >> 3);
                int q1 = ((kb + 2) & 6) + ((kb + 2) >> 3);
                uint32_t* A = (uint32_t*)(rsm + RS_A + ks * KSTRIDE) + row * 8;
                A[q0] = packbf(z0, z1);
                A[q1] = packbf(z2, z3);
            }
        }
    };

    #pragma unroll 1
    for (int c = 0; c < 4; ++c) {
        if (c) __syncthreads();
        conv(c);
        __syncthreads();
        #pragma unroll
        for (int ks = 0; ks < 8; ++ks) {
            const char* hb = rsm + RS_A + ks * KSTRIDE + i4 * 8;
            int r = w * 16 + gl;
            uint2 u = *(const uint2*)(hb + r * 32);
            uint2 v = *(const uint2*)(hb + (r + 8) * 32);
            uint32_t a[4] = {u.x, v.x, u.y, v.y};
            const char* bb = rsm + RS_U + (c * 8 + ks) * 1024 + i4 * 8;
            #pragma unroll
            for (int nt = 0; nt < 4; ++nt) {
                uint2 b = *(const uint2*)(bb + (nt * 8 + gl) * 32);
                uint32_t br[2] = {b.x, b.y};
                mma16816(acc[nt], a, br);
            }
        }
    }

    #pragma unroll
    for (int p = 0; p < 4; ++p) {
        float v = znp[p];
        v += __shfl_xor_sync(~0u, v, 1);
        v += __shfl_xor_sync(~0u, v, 2);
        v += __shfl_xor_sync(~0u, v, 4);
        if (c8 == 0) s_zn[p * 32 + w * 4 + rq] = v;
    }
    __syncthreads();   // all warps past MMA -> RS_A reusable as coord

    float* crdH = (float*)(rsm + RS_A);
    int r0 = w * 16 + gl, r1 = r0 + 8;
    float zun0 = 0.f, zun1 = 0.f;
    #pragma unroll
    for (int nt = 0; nt < 4; ++nt) {
        zun0 += acc[nt][0] * acc[nt][0] + acc[nt][1] * acc[nt][1];
        zun1 += acc[nt][2] * acc[nt][2] + acc[nt][3] * acc[nt][3];
    }
    zun0 += __shfl_xor_sync(~0u, zun0, 1); zun0 += __shfl_xor_sync(~0u, zun0, 2);
    zun1 += __shfl_xor_sync(~0u, zun1, 1); zun1 += __shfl_xor_sync(~0u, zun1, 2);
    #pragma unroll
    for (int nt = 0; nt < 4; ++nt) {
        int cc = nt * 8 + 2 * i4;
        *(float2*)&crdH[r0 * CRD_S + cc] =
            make_float2(acc[nt][0] + dUs[cc], acc[nt][1] + dUs[cc + 1]);
        *(float2*)&crdH[r1 * CRD_S + cc] =
            make_float2(acc[nt][2] + dUs[cc], acc[nt][3] + dUs[cc + 1]);
    }

    // fused secant
    if (i4 < 2) {
        int r = (i4 == 0) ? r0 : r1;
        float zun = (i4 == 0) ? zun0 : zun1;
        float zp = s_zn[r] - zun;
        float egz = expf(-GAMMA * zun);
        float x_m2 = zp * GUESS_RATIO, x_m1 = zp;
        float f_m2 = secf(x_m2, egz, zp);
        for (int it = 0; it < 100; ++it) {
            float f_m1 = secf(x_m1, egz, zp);
            float fd = f_m1 - f_m2;
            if (fabsf(fd) < TOLF) fd = (fd >= 0.f) ? TOLF : -TOLF;
            float x = x_m1 - f_m1 * (x_m1 - x_m2) / fd;
            float st = fabsf(x - x_m1);
            x_m2 = x_m1; f_m2 = f_m1; x_m1 = x;
            if (st < 3e-6f * fabsf(x) + TOLF) break;
        }
        g_kv[n0 + r] = expf(-GAMMA * (zun + x_m1));
    }
    __syncthreads();   // coord tile complete

    // fused H generation -> g_H
    {
        int row = tid >> 1, gh = tid & 1;
        const float* cm = &crdH[row * CRD_S];
        uint32_t* Hb = g_H + ((size_t)blockIdx.x * NKS) * 128 * 8;
        #pragma unroll 1
        for (int ks = 0; ks < NKS; ++ks) {
            int kbase = ks * 16;
            uint32_t wv[4];
            #pragma unroll
            for (int qq = 0; qq < 4; ++qq) {
                int q = gh * 4 + qq;
                int kb = kbase + 2 * (q >> 1) + 8 * (q & 1);
                uint32_t p0 = iup[kb], p1 = iup[kb + 1];
                wv[qq] = packbf(cm[p0 & 255] * cm[p0 >> 8], cm[p1 & 255] * cm[p1 >> 8]);
            }
            *(uint4*)(Hb + ((size_t)ks * 128 + row) * 8 + gh * 4) =
                make_uint4(wv[0], wv[1], wv[2], wv[3]);
        }
    }
}

// ---------------- kernel F: copy uncovered rows ----------------
__global__ __launch_bounds__(256) void k_fill(const float* __restrict__ Z_all,
                                              float* __restrict__ out, int rows) {
    int wi = (blockIdx.x * 256 + threadIdx.x) >> 5;
    int lane = threadIdx.x & 31;
    int r0 = wi * 32;
    if (r0 >= rows) return;
    uint32_t need = ~g_cover[wi];
    if (r0 + 32 > rows) need &= (1u << (rows - r0)) - 1u;
    while (need) {
        int b = __ffs(need) - 1;
        need &= need - 1;
        size_t r = (size_t)(r0 + b);
        const float4* z = (const float4*)(Z_all + r * D_DIM);
        float4* o = (float4*)(out + r * D_DIM);
        #pragma unroll
        for (int i = 0; i < 4; ++i) o[lane + 32 * i] = z[lane + 32 * i];
    }
}

// ---------------- kernel C: HMMA GEMM, mbar-only pipeline ----------------
#define OFF_B   0               // 4 * 12288
#define OFF_HR  49152           // 4 * 12288
#define OFF_CHG 98304
#define OFF_KV  98816
#define OFF_CHC 99328
#define OFF_MB  99840           // 4 full + 4 empty = 64 B
#define SMEM_SZ 99968

__global__ __launch_bounds__(256, 2) void k_gemm(
    const float* __restrict__ Z_all, const int* __restrict__ choice,
    float* __restrict__ out, int N) {

    extern __shared__ __align__(16) char smem[];
    uint32_t sb = smem_u32(smem);
    int tid = threadIdx.x;
    int d0 = blockIdx.x * 128;
    int m0 = blockIdx.y * MT;

    float* chgS = (float*)(smem + OFF_CHG);
    float* kvS  = (float*)(smem + OFF_KV);
    int*   chcS = (int*)(smem + OFF_CHC);

    uint32_t mbf[4] = {sb + OFF_MB,      sb + OFF_MB + 8,  sb + OFF_MB + 16, sb + OFF_MB + 24};
    uint32_t mbe[4] = {sb + OFF_MB + 32, sb + OFF_MB + 40, sb + OFF_MB + 48, sb + OFF_MB + 56};
    const char* Vbase = (const char*)g_Vb + (size_t)blockIdx.x * NG * GB;
    const char* Hbase = (const char*)g_H + (size_t)blockIdx.y * NKS * STB;

    if (tid == 0) {
        #pragma unroll
        for (int s = 0; s < 4; ++s) { MBAR_INIT(mbf[s], 1); MBAR_INIT(mbe[s], 8); }
        FENCE_ASYNC();
        #pragma unroll
        for (int gq = 0; gq < 3; ++gq) {
            MBAR_EXPECT_TX(mbf[gq], 2 * GB);
            bulk_g2s(sb + OFF_B  + gq * GB, Vbase + (size_t)gq * GB, GB, mbf[gq]);
            bulk_g2s(sb + OFF_HR + gq * GB, Hbase + (size_t)gq * GB, GB, mbf[gq]);
        }
    }

    if (tid < 128) {
        chgS[tid] = g_change[d0 + tid];
        int gm = m0 + tid;
        kvS[tid]  = (gm < N) ? g_kv[gm] : 0.f;
        chcS[tid] = (gm < N) ? choice[gm] : 0;
    }
    __syncthreads();

    int lane = tid & 31, wid = tid >> 5;
    int gl = lane >> 2, i4 = lane & 3;
    int warp_m0 = (wid >> 1) * 32;
    int warp_n0 = (wid & 1) * 64;

    float acc[2][8][4] = {};

    #pragma unroll 1
    for (int g = 0; g < NG; ++g) {
        if (tid == 0 && g + 3 < NG) {
            int gf = g + 3;
            int slot = gf & 3, u = gf >> 2;
            if (u >= 1) MBAR_WAIT(mbe[slot], (u - 1) & 1);   // slot consumed
            MBAR_EXPECT_TX(mbf[slot], 2 * GB);
            bulk_g2s(sb + OFF_B  + slot * GB, Vbase + (size_t)gf * GB, GB, mbf[slot]);
            bulk_g2s(sb + OFF_HR + slot * GB, Hbase + (size_t)gf * GB, GB, mbf[slot]);
        }
        MBAR_WAIT(mbf[g & 3], (g >> 2) & 1);

        if (g == NG - 3) {   // L2 prefetch of epilogue Z rows
            #pragma unroll
            for (int mt = 0; mt < 2; ++mt)
                #pragma unroll
                for (int rr = 0; rr < 2; ++rr) {
                    int r = warp_m0 + mt * 16 + gl + rr * 8;
                    if (m0 + r < N) {
                        const float* p = Z_all + (size_t)chcS[r] * D_DIM + d0 + warp_n0;
                        asm volatile("prefetch.global.L2 [%0];" :: "l"(p));
                        asm volatile("prefetch.global.L2 [%0];" :: "l"(p + 32));
                    }
                }
        }

        const char* hbuf = smem + OFF_HR + (g & 3) * GB;
        const char* bbuf = smem + OFF_B  + (g & 3) * GB;
        #pragma unroll
        for (int sl = 0; sl < GS; ++sl) {
            const char* hb = hbuf + sl * STB + i4 * 8;
            const char* bb = bbuf + sl * STB + i4 * 8;
            uint32_t a[2][4];
            #pragma unroll
            for (int mt = 0; mt < 2; ++mt) {
                int r = warp_m0 + mt * 16 + gl;
                uint2 u = *(const uint2*)(hb + r * 32);
                uint2 v = *(const uint2*)(hb + (r + 8) * 32);
                a[mt][0] = u.x; a[mt][1] = v.x; a[mt][2] = u.y; a[mt][3] = v.y;
            }
            #pragma unroll
            for (int nt = 0; nt < 8; ++nt) {
                int n = warp_n0 + nt * 8 + gl;
                uint2 b = *(const uint2*)(bb + n * 32);
                uint32_t br[2] = {b.x, b.y};
                mma16816(acc[0][nt], a[0], br);
                mma16816(acc[1][nt], a[1], br);
            }
        }
        if (lane == 0) MBAR_ARRIVE(mbe[g & 3]);   // warp done with this slot
    }

    #pragma unroll
    for (int mt = 0; mt < 2; ++mt) {
        #pragma unroll
        for (int rr = 0; rr < 2; ++rr) {
            int r = warp_m0 + mt * 16 + gl + rr * 8;
            int gm = m0 + r;
            if (gm >= N) continue;
            float kv = kvS[r];
            size_t base = (size_t)chcS[r] * D_DIM + d0 + warp_n0 + 2 * i4;
            #pragma unroll
            for (int nt = 0; nt < 8; ++nt) {
                size_t idx = base + nt * 8;
                int nl = warp_n0 + nt * 8 + 2 * i4;
                float2 z = *(const float2*)&Z_all[idx];
                float2 o;
                o.x = z.x + kv * (chgS[nl]     + acc[mt][nt][rr * 2]);
                o.y = z.y + kv * (chgS[nl + 1] + acc[mt][nt][rr * 2 + 1]);
                *(float2*)&out[idx] = o;
            }
        }
    }
}

// ---------------- launch ----------------
extern "C" void kernel_launch(void* const* d_in, const int* in_sizes, int n_in,
                              void* d_out, int out_size) {
    const float* Z_all = (const float*)d_in[0];
    const float* U     = (const float*)d_in[1];
    const float* V     = (const float*)d_in[2];
    const float* zmu   = (const float*)d_in[3];
    const float* xc    = (const float*)d_in[4];
    const int*   choice= (const int*)d_in[5];
    int N = in_sizes[5];
    float* out = (float*)d_out;
    int rows = out_size / D_DIM;
    int mblks = (N + MT - 1) / MT;

    cudaFuncSetAttribute(k_gemm, cudaFuncAttributeMaxDynamicSharedMemorySize, SMEM_SZ);
    cudaFuncSetAttribute(k_rowstats, cudaFuncAttributeMaxDynamicSharedMemorySize, RS_SMEM);

    k_init<<<1, 512>>>(U, zmu, xc);
    k_prepV<<<512, 288>>>(V);
    k_prepU<<<32, 256>>>(U);
    k_rowstats<<<mblks, 256, RS_SMEM>>>(Z_all, zmu, choice, N);
    k_fill<<<(rows + 255) / 256, 256>>>(Z_all, out, rows);
    dim3 grid(4, mblks);
    k_gemm<<<grid, 256, SMEM_SZ>>>(Z_all, choice, out, N);
}